// round 1
// baseline (speedup 1.0000x reference)
#include <cuda_runtime.h>
#include <cstddef>

// Problem constants (H = V = O = 4096, M = 104, DM = 1)
#define H 4096
#define M_STACK 104

// Scratch for the hidden vector h between the two kernels.
__device__ float g_h[H];

// ---------------------------------------------------------------------------
// Kernel 1: h = tanh(W_ih @ emb + b_ih + W_hh @ hbar + b_hh)
//   emb  = E[idx, :]                        (row of E, contiguous)
//   hbar = W_sh[:,0]*stack[0] + b_sh + hidden0
// 512 blocks x 256 threads; each block stages emb+hbar in smem, then
// one warp per output row (8 rows/block).
// ---------------------------------------------------------------------------
__global__ __launch_bounds__(256) void srnn_hidden_kernel(
    const int* __restrict__ inp,
    const float* __restrict__ hidden0,
    const float* __restrict__ stack,
    const float* __restrict__ E,
    const float* __restrict__ W_ih,
    const float* __restrict__ b_ih,
    const float* __restrict__ W_hh,
    const float* __restrict__ b_hh,
    const float* __restrict__ W_sh,
    const float* __restrict__ b_sh,
    float* __restrict__ out_hidden)   // d_out + 4096
{
    __shared__ float s_emb[H];
    __shared__ float s_hbar[H];

    const int tid = threadIdx.x;
    const int idx = inp[0];
    const float s0 = stack[0];

    const float4* __restrict__ E4   = (const float4*)(E + (size_t)idx * H);
    const float4* __restrict__ h04  = (const float4*)hidden0;
    const float4* __restrict__ bsh4 = (const float4*)b_sh;
    const float4* __restrict__ wsh4 = (const float4*)W_sh;
    float4* s_emb4  = (float4*)s_emb;
    float4* s_hbar4 = (float4*)s_hbar;

#pragma unroll
    for (int k = 0; k < 4; ++k) {
        const int v = tid + k * 256;           // float4 index 0..1023
        s_emb4[v] = E4[v];
        const float4 a = h04[v];
        const float4 b = bsh4[v];
        const float4 w = wsh4[v];
        float4 hb;
        hb.x = fmaf(w.x, s0, a.x + b.x);
        hb.y = fmaf(w.y, s0, a.y + b.y);
        hb.z = fmaf(w.z, s0, a.z + b.z);
        hb.w = fmaf(w.w, s0, a.w + b.w);
        s_hbar4[v] = hb;
    }
    __syncthreads();

    const int warp = tid >> 5;
    const int lane = tid & 31;
    const int row  = blockIdx.x * 8 + warp;

    const float4* __restrict__ A4 = (const float4*)(W_ih + (size_t)row * H);
    const float4* __restrict__ B4 = (const float4*)(W_hh + (size_t)row * H);

    float acc = 0.0f;
#pragma unroll 8
    for (int k = 0; k < 32; ++k) {
        const int v = lane + k * 32;
        const float4 a = A4[v];
        const float4 x = s_emb4[v];
        acc += a.x * x.x + a.y * x.y + a.z * x.z + a.w * x.w;
        const float4 b = B4[v];
        const float4 y = s_hbar4[v];
        acc += b.x * y.x + b.y * y.y + b.z * y.z + b.w * y.w;
    }
#pragma unroll
    for (int off = 16; off > 0; off >>= 1)
        acc += __shfl_xor_sync(0xFFFFFFFFu, acc, off);

    if (lane == 0) {
        const float h = tanhf(acc + b_ih[row] + b_hh[row]);
        g_h[row] = h;
        out_hidden[row] = h;   // "hidden" output slice
    }
}

// ---------------------------------------------------------------------------
// Kernel 2:
//   blocks 0..511 : output = sigmoid(W_y @ h + b_y)   (8 rows/block, smem-staged h)
//   block 512     : a = softmax(W_a @ h + b_a); new_elt = sigmoid(W_n @ h + b_n);
//                   new_stack blend; weights = sum(a)
// ---------------------------------------------------------------------------
__global__ __launch_bounds__(256) void srnn_output_kernel(
    const float* __restrict__ W_y,
    const float* __restrict__ b_y,
    const float* __restrict__ W_n,
    const float* __restrict__ b_n,
    const float* __restrict__ W_a,
    const float* __restrict__ b_a,
    const float* __restrict__ stack,
    float* __restrict__ d_out)
{
    const int tid  = threadIdx.x;
    const int warp = tid >> 5;
    const int lane = tid & 31;

    if (blockIdx.x < 512) {
        __shared__ float s_h[H];
        float4* s_h4 = (float4*)s_h;
        const float4* gh4 = (const float4*)g_h;
#pragma unroll
        for (int k = 0; k < 4; ++k) {
            const int v = tid + k * 256;
            s_h4[v] = gh4[v];
        }
        __syncthreads();

        const int row = blockIdx.x * 8 + warp;
        const float4* __restrict__ A4 = (const float4*)(W_y + (size_t)row * H);

        float acc = 0.0f;
#pragma unroll 8
        for (int k = 0; k < 32; ++k) {
            const int v = lane + k * 32;
            const float4 a = A4[v];
            const float4 x = s_h4[v];
            acc += a.x * x.x + a.y * x.y + a.z * x.z + a.w * x.w;
        }
#pragma unroll
        for (int off = 16; off > 0; off >>= 1)
            acc += __shfl_xor_sync(0xFFFFFFFFu, acc, off);

        if (lane == 0) {
            const float z = acc + b_y[row];
            d_out[row] = 1.0f / (1.0f + expf(-z));   // "output" slice
        }
    } else {
        // Tiny tail block: 3 dot products over h, softmax, stack blend.
        __shared__ float s_dots[3];
        __shared__ float s_aw0, s_aw1, s_ne;

        if (warp < 3) {
            const float* __restrict__ Wrow =
                (warp < 2) ? (W_a + (size_t)warp * H) : W_n;
            const float4* __restrict__ A4 = (const float4*)Wrow;
            const float4* __restrict__ h4 = (const float4*)g_h;
            float acc = 0.0f;
#pragma unroll 8
            for (int k = 0; k < 32; ++k) {
                const int v = lane + k * 32;
                const float4 a = A4[v];
                const float4 x = h4[v];
                acc += a.x * x.x + a.y * x.y + a.z * x.z + a.w * x.w;
            }
#pragma unroll
            for (int off = 16; off > 0; off >>= 1)
                acc += __shfl_xor_sync(0xFFFFFFFFu, acc, off);
            if (lane == 0) s_dots[warp] = acc;
        }
        __syncthreads();

        if (tid == 0) {
            const float a0 = s_dots[0] + b_a[0];
            const float a1 = s_dots[1] + b_a[1];
            const float m  = fmaxf(a0, a1);
            const float e0 = expf(a0 - m);
            const float e1 = expf(a1 - m);
            const float inv = 1.0f / (e0 + e1);
            const float aw0 = e0 * inv;
            const float aw1 = e1 * inv;
            s_aw0 = aw0;
            s_aw1 = aw1;
            s_ne  = 1.0f / (1.0f + expf(-(s_dots[2] + b_n[0])));
            d_out[2 * H + M_STACK] = aw0 + aw1;       // "weights" scalar
        }
        __syncthreads();

        if (tid < M_STACK) {
            const float push = (tid == 0) ? s_ne : stack[tid - 1];
            const float pop  = (tid < M_STACK - 1) ? stack[tid + 1] : 0.0f;
            d_out[2 * H + tid] = s_aw0 * push + s_aw1 * pop;  // "new_stack"
        }
    }
}

// ---------------------------------------------------------------------------
// Launch
// Inputs (metadata order): 0 inp(int), 1 hidden0, 2 stack, 3 E, 4 W_ih,
// 5 b_ih, 6 W_hh, 7 b_hh, 8 W_y, 9 b_y, 10 W_n, 11 b_n, 12 W_a, 13 b_a,
// 14 W_sh, 15 b_sh.
// Output layout: [output 4096 | hidden 4096 | new_stack 104 | weights 1]
// ---------------------------------------------------------------------------
extern "C" void kernel_launch(void* const* d_in, const int* in_sizes, int n_in,
                              void* d_out, int out_size)
{
    (void)in_sizes; (void)n_in; (void)out_size;

    const int*   inp     = (const int*)  d_in[0];
    const float* hidden0 = (const float*)d_in[1];
    const float* stack   = (const float*)d_in[2];
    const float* E       = (const float*)d_in[3];
    const float* W_ih    = (const float*)d_in[4];
    const float* b_ih    = (const float*)d_in[5];
    const float* W_hh    = (const float*)d_in[6];
    const float* b_hh    = (const float*)d_in[7];
    const float* W_y     = (const float*)d_in[8];
    const float* b_y     = (const float*)d_in[9];
    const float* W_n     = (const float*)d_in[10];
    const float* b_n     = (const float*)d_in[11];
    const float* W_a     = (const float*)d_in[12];
    const float* b_a     = (const float*)d_in[13];
    const float* W_sh    = (const float*)d_in[14];
    const float* b_sh    = (const float*)d_in[15];

    float* out = (float*)d_out;

    srnn_hidden_kernel<<<512, 256>>>(inp, hidden0, stack, E, W_ih, b_ih,
                                     W_hh, b_hh, W_sh, b_sh, out + H);
    srnn_output_kernel<<<513, 256>>>(W_y, b_y, W_n, b_n, W_a, b_a,
                                     stack, out);
}